// round 10
// baseline (speedup 1.0000x reference)
#include <cuda_runtime.h>
#include <cstdint>

// ============================================================================
// Bit-exact JAX threefry2x32 (partitionable) — rel_err = 0.0 verified R2-R9.
// R10 = R9 base (unroll-4, occ 59%, issue 75.1%, alu 92.5% = binder)
//     + R6's 5-of-20 mul.wide rotate conversion (issue-neutral, alu-share
//       0.616 -> ~0.57 => issue ceiling 81% -> 87.7%). R6 failed only because
//       occ was 47%; R9's occupancy unlocks the higher ceiling.
// ============================================================================

#define FULLM 0xffffffffu

struct TKey { uint32_t a, b, c; };

__device__ __forceinline__ TKey mk_key(uint32_t k0, uint32_t k1) {
    TKey k; k.a = k0; k.b = k1; k.c = k0 ^ k1 ^ 0x1BD11BDAu; return k;
}

// ---- plain threefry (setup kernel only)
#define TF_ROUND(x0, x1, r) { x0 += x1; x1 = __funnelshift_l(x1, x1, (r)); x1 ^= x0; }
#define TF_R4A(x0, x1) { TF_ROUND(x0,x1,13) TF_ROUND(x0,x1,15) TF_ROUND(x0,x1,26) TF_ROUND(x0,x1,6) }
#define TF_R4B(x0, x1) { TF_ROUND(x0,x1,17) TF_ROUND(x0,x1,29) TF_ROUND(x0,x1,16) TF_ROUND(x0,x1,24) }

__device__ __forceinline__ void tf_pair(const TKey k, uint32_t c0, uint32_t c1,
                                        uint32_t& o0, uint32_t& o1) {
    uint32_t x0 = c0 + k.a, x1 = c1 + k.b;
    TF_R4A(x0, x1); x0 += k.b; x1 += k.c + 1u;
    TF_R4B(x0, x1); x0 += k.c; x1 += k.a + 2u;
    TF_R4A(x0, x1); x0 += k.a; x1 += k.b + 3u;
    TF_R4B(x0, x1); x0 += k.b; x1 += k.c + 4u;
    TF_R4A(x0, x1); x0 += k.c; x1 += k.a + 5u;
    o0 = x0; o1 = x1;
}

// ---- add on the IMAD pipe (`one` = opaque runtime 1)
__device__ __forceinline__ uint32_t addf(uint32_t a, uint32_t b, uint32_t one) {
    uint32_t d;
    asm("mad.lo.u32 %0, %1, %2, %3;" : "=r"(d) : "r"(a), "r"(one), "r"(b));
    return d;
}

// ---- rotate via wide-mul (IMAD pipe, single issue) + fused (lo|hi)^x0 LOP3
__device__ __forceinline__ uint32_t rotm_xor(uint32_t x1, uint32_t pow, uint32_t x0) {
    uint64_t w;
    asm("mul.wide.u32 %0, %1, %2;" : "=l"(w) : "r"(x1), "r"(pow));
    const uint32_t lo = (uint32_t)w, hi = (uint32_t)(w >> 32);
    return (lo | hi) ^ x0;          // single fused LOP3
}

struct TSched {
    uint32_t a, b, c;
    uint32_t c1, a2, b3, c4, a5;   // k.c+1, k.a+2, k.b+3, k.c+4, k.a+5
};

__device__ __forceinline__ TSched mk_sched(uint32_t a, uint32_t b, uint32_t c) {
    TSched s; s.a = a; s.b = b; s.c = c;
    s.c1 = c + 1u; s.a2 = a + 2u; s.b3 = b + 3u; s.c4 = c + 4u; s.a5 = a + 5u;
    return s;
}

#define TFF_ROUND(x0, x1, r) { x0 = addf(x0, x1, one); x1 = __funnelshift_l(x1, x1, (r)); x1 ^= x0; }
#define TFF_ROUNDM(x0, x1, POW) { x0 = addf(x0, x1, one); x1 = rotm_xor(x1, POW, x0); }

#define TFF_R4A(x0, x1) { TFF_ROUNDM(x0,x1,p13) TFF_ROUND(x0,x1,15) TFF_ROUND(x0,x1,26) TFF_ROUND(x0,x1,6) }
#define TFF_R4B(x0, x1) { TFF_ROUNDM(x0,x1,p17) TFF_ROUND(x0,x1,29) TFF_ROUND(x0,x1,16) TFF_ROUND(x0,x1,24) }

// threefry2x32 at counter (0, idx): alu = 15 SHF + 20 LOP3 + 1 XOR,
// imad = 31 adds + 5 wide-muls.
__device__ __forceinline__ uint32_t tff_bits(const TSched k, uint32_t idx,
                                             uint32_t one, uint32_t p13, uint32_t p17) {
    uint32_t x0 = k.a, x1 = addf(idx, k.b, one);
    TFF_R4A(x0, x1); x0 = addf(x0, k.b, one); x1 = addf(x1, k.c1, one);
    TFF_R4B(x0, x1); x0 = addf(x0, k.c, one); x1 = addf(x1, k.a2, one);
    TFF_R4A(x0, x1); x0 = addf(x0, k.a, one); x1 = addf(x1, k.b3, one);
    TFF_R4B(x0, x1); x0 = addf(x0, k.b, one); x1 = addf(x1, k.c4, one);
    TFF_R4A(x0, x1); x0 = addf(x0, k.c, one); x1 = addf(x1, k.a5, one);
    return x0 ^ x1;
}

// Pre-shifted threshold: uniform(bits) < e  <=>  bits < (ceil(e*2^23) << 9).
__device__ __forceinline__ uint32_t thresh_shifted(float e) {
    return ((uint32_t)ceil((double)e * 8388608.0)) << 9;
}

// ============================================================================
// Per-channel key cache (keys depend only on channel c).
// ============================================================================

__device__ uint32_t g_keys[4][16];

__global__ void key_setup_kernel() {
    const int c = threadIdx.x;
    if (c >= 4) return;
    uint32_t t0, t1;
    const TKey root = mk_key(0u, 42u);
    tf_pair(root, 0u, (uint32_t)c, t0, t1);
    const TKey kc = mk_key(t0, t1);

    tf_pair(kc, 0u, 0u, t0, t1); const TKey s1 = mk_key(t0, t1);
    tf_pair(kc, 0u, 1u, t0, t1); const TKey s2 = mk_key(t0, t1);
    tf_pair(kc, 0u, 2u, t0, t1); const TKey s3 = mk_key(t0, t1);

    tf_pair(s1, 0u, 0u, t0, t1); const TKey sub_a = mk_key(t0, t1);
    tf_pair(sub_a, 0u, 1u, t0, t1); const TKey k_subdata = mk_key(t0, t1);
    tf_pair(s1, 0u, 1u, t0, t1); const TKey k_submask = mk_key(t0, t1);

    tf_pair(s3, 0u, 0u, t0, t1); const TKey k_insflag = mk_key(t0, t1);
    tf_pair(s3, 0u, 1u, t0, t1); const TKey ins_b = mk_key(t0, t1);
    tf_pair(ins_b, 0u, 1u, t0, t1); const TKey k_inssym = mk_key(t0, t1);

    uint32_t* kp = g_keys[c];
    kp[0] = k_submask.a; kp[1] = k_submask.b; kp[2] = k_submask.c;
    kp[3] = s2.a;        kp[4] = s2.b;        kp[5] = s2.c;
    kp[6] = k_subdata.a; kp[7] = k_subdata.b; kp[8] = k_subdata.c;
    kp[9] = k_insflag.a; kp[10] = k_insflag.b; kp[11] = k_insflag.c;
    kp[12] = k_inssym.a; kp[13] = k_inssym.b; kp[14] = k_inssym.c;
}

// ============================================================================
// Warp-per-(row, channel); lane owns 16 contiguous elements.
// ============================================================================

__global__ void __launch_bounds__(256)
channel_warp_kernel(const float* __restrict__ x, float* __restrict__ out, int B) {
    const int gw = (int)((blockIdx.x * blockDim.x + threadIdx.x) >> 5);
    const int lane = threadIdx.x & 31;
    if (gw >= B * 4) return;
    const int c = gw & 3;
    const int b = gw >> 2;

    const uint32_t KsubS = thresh_shifted(0.02f);
    const uint32_t KdelS = thresh_shifted(0.01f);
    const uint32_t KinsS = thresh_shifted(0.01f);

    const uint32_t* kp = g_keys[c];
    const uint32_t one = (kp[0] >> 31) | 1u;       // opaque runtime 1
    const uint32_t p13 = (1u << 13) * one;         // opaque 2^13
    const uint32_t p17 = (1u << 17) * one;         // opaque 2^17
    const TSched kSubM = mk_sched(kp[0], kp[1], kp[2]);
    const TSched kDel  = mk_sched(kp[3], kp[4], kp[5]);

    // ---- load my 16 elements, +1.0f folded in (mod threshold becomes 5)
    float v[16];
    const float4* __restrict__ xr4 =
        (const float4*)(x + (size_t)b * 512 + (size_t)lane * 16);
    #pragma unroll
    for (int q = 0; q < 4; q++) {
        const float4 f = xr4[q];
        v[q * 4 + 0] = f.x + 1.0f; v[q * 4 + 1] = f.y + 1.0f;
        v[q * 4 + 2] = f.z + 1.0f; v[q * 4 + 3] = f.w + 1.0f;
    }

    // ---- phase 1: sub-need + keep flags (unroll 4, ILP=8)
    const uint32_t base = (uint32_t)b * 512u + (uint32_t)lane * 16u;
    uint32_t keepmask = 0u, subneed = 0u;
    {
        uint32_t bit = 1u;
        #pragma unroll 4
        for (int i = 0; i < 16; i++) {
            const uint32_t idx = base + (uint32_t)i;
            const uint32_t bs = tff_bits(kSubM, idx, one, p13, p17);
            const uint32_t bd = tff_bits(kDel,  idx, one, p13, p17);
            if (bs < KsubS)  subneed  |= bit;
            if (bd >= KdelS) keepmask |= bit;
            bit <<= 1;
        }
    }

    // ---- deferred sub draws: per-lane bit loop, 2-bit packed deltas
    uint32_t subdelta = 0u;
    {
        const TSched kSubD = mk_sched(kp[6], kp[7], kp[8]);
        uint32_t m = subneed;
        while (m) {
            const int i = __ffs(m) - 1; m &= m - 1u;
            const uint32_t db = tff_bits(kSubD, base + (uint32_t)i, one, p13, p17);
            subdelta |= (db & 3u) << (2 * i);
        }
    }

    // ---- scan 1: exclusive scan of keep counts -> compacted offset
    const int kn = __popc(keepmask);
    int incl = kn;
    #pragma unroll
    for (int d = 1; d < 32; d <<= 1) {
        const int nv = __shfl_up_sync(FULLM, incl, d);
        if (lane >= d) incl += nv;
    }
    const int ofs = incl - kn;

    // ---- phase 2: ins flags at compacted indices (iterative j, unroll 4)
    const uint32_t insbase = (uint32_t)b * 514u;
    uint32_t insmask = 0u;
    {
        const TSched kInsF = mk_sched(kp[9], kp[10], kp[11]);
        uint32_t km = keepmask, bit = 1u;
        uint32_t j = insbase + (uint32_t)ofs;
        #pragma unroll 4
        for (int i = 0; i < 16; i++) {
            const uint32_t bi = tff_bits(kInsF, j, one, p13, p17);
            if (bi < KinsS) insmask |= bit;
            j += km & 1u; km >>= 1; bit <<= 1;
        }
    }
    insmask &= keepmask;

    // ---- scan 2: output offsets
    const int myout = kn + __popc(insmask);
    int incl2 = myout;
    #pragma unroll
    for (int d = 1; d < 32; d <<= 1) {
        const int nv = __shfl_up_sync(FULLM, incl2, d);
        if (lane >= d) incl2 += nv;
    }
    const int outofs = incl2 - myout;
    const int total_out = __shfl_sync(FULLM, incl2, 31);

    float* __restrict__ orow = out + ((size_t)b * 4 + (size_t)c) * 514;

    // ---- write kept elements: full unroll (static v[i]), branch-free positions
    #pragma unroll
    for (int i = 0; i < 16; i++) {
        const uint32_t below = (1u << i) - 1u;
        const int pos = outofs + __popc(keepmask & below) + __popc(insmask & below);
        float vv = v[i] + (float)((subdelta >> (2 * i)) & 3u);   // in [1,7]
        if (vv >= 5.0f) vv -= 4.0f;                               // exact mod-4 (+1 folded)
        if (((keepmask >> i) & 1u) && pos < 514) orow[pos] = vv;
    }

    // ---- inserted symbols: rare per-lane bit loop
    {
        const TSched kInsS2 = mk_sched(kp[12], kp[13], kp[14]);
        uint32_t m = insmask;
        while (m) {
            const int i = __ffs(m) - 1; m &= m - 1u;
            const uint32_t below = (1u << i) - 1u;
            const int nk = __popc(keepmask & below);
            const uint32_t j = insbase + (uint32_t)(ofs + nk);
            const int pos = outofs + nk + __popc(insmask & below) + 1;
            const uint32_t sb = tff_bits(kInsS2, j, one, p13, p17);
            if (pos < 514) orow[pos] = (float)(sb & 3u) + 1.0f;
        }
    }

    // ---- tail padding: 0.0 (= -1 + 1)
    for (int p = total_out + lane; p < 514; p += 32) orow[p] = 0.0f;
}

extern "C" void kernel_launch(void* const* d_in, const int* in_sizes, int n_in,
                              void* d_out, int out_size) {
    const float* x = (const float*)d_in[0];   // segment_en [B, 512]
    float* out = (float*)d_out;               // [B, 4, 514] float32
    const int B = in_sizes[0] / 512;

    key_setup_kernel<<<1, 4>>>();

    const long long total_threads = (long long)B * 4 * 32;
    const int block = 256;
    const int grid = (int)((total_threads + block - 1) / block);
    channel_warp_kernel<<<grid, block>>>(x, out, B);
}

// round 11
// speedup vs baseline: 1.0011x; 1.0011x over previous
#include <cuda_runtime.h>
#include <cstdint>

// ============================================================================
// Bit-exact JAX threefry2x32 (partitionable) — rel_err = 0.0 verified R2-R10.
// R11 = R10 (mul.wide rotates: alu share 0.62->0.57, issue ceiling 88%)
//     + __launch_bounds__(256,5) to pin regs <=51 and restore the occ~59%
//       that R10 lost (58 regs -> 47% occ -> issue starved at 71.8%).
// ============================================================================

#define FULLM 0xffffffffu

struct TKey { uint32_t a, b, c; };

__device__ __forceinline__ TKey mk_key(uint32_t k0, uint32_t k1) {
    TKey k; k.a = k0; k.b = k1; k.c = k0 ^ k1 ^ 0x1BD11BDAu; return k;
}

// ---- plain threefry (setup kernel only)
#define TF_ROUND(x0, x1, r) { x0 += x1; x1 = __funnelshift_l(x1, x1, (r)); x1 ^= x0; }
#define TF_R4A(x0, x1) { TF_ROUND(x0,x1,13) TF_ROUND(x0,x1,15) TF_ROUND(x0,x1,26) TF_ROUND(x0,x1,6) }
#define TF_R4B(x0, x1) { TF_ROUND(x0,x1,17) TF_ROUND(x0,x1,29) TF_ROUND(x0,x1,16) TF_ROUND(x0,x1,24) }

__device__ __forceinline__ void tf_pair(const TKey k, uint32_t c0, uint32_t c1,
                                        uint32_t& o0, uint32_t& o1) {
    uint32_t x0 = c0 + k.a, x1 = c1 + k.b;
    TF_R4A(x0, x1); x0 += k.b; x1 += k.c + 1u;
    TF_R4B(x0, x1); x0 += k.c; x1 += k.a + 2u;
    TF_R4A(x0, x1); x0 += k.a; x1 += k.b + 3u;
    TF_R4B(x0, x1); x0 += k.b; x1 += k.c + 4u;
    TF_R4A(x0, x1); x0 += k.c; x1 += k.a + 5u;
    o0 = x0; o1 = x1;
}

// ---- add on the IMAD pipe (`one` = opaque runtime 1)
__device__ __forceinline__ uint32_t addf(uint32_t a, uint32_t b, uint32_t one) {
    uint32_t d;
    asm("mad.lo.u32 %0, %1, %2, %3;" : "=r"(d) : "r"(a), "r"(one), "r"(b));
    return d;
}

// ---- rotate via wide-mul (IMAD pipe, single issue) + fused (lo|hi)^x0 LOP3
__device__ __forceinline__ uint32_t rotm_xor(uint32_t x1, uint32_t pow, uint32_t x0) {
    uint64_t w;
    asm("mul.wide.u32 %0, %1, %2;" : "=l"(w) : "r"(x1), "r"(pow));
    const uint32_t lo = (uint32_t)w, hi = (uint32_t)(w >> 32);
    return (lo | hi) ^ x0;          // single fused LOP3
}

struct TSched {
    uint32_t a, b, c;
    uint32_t c1, a2, b3, c4, a5;   // k.c+1, k.a+2, k.b+3, k.c+4, k.a+5
};

__device__ __forceinline__ TSched mk_sched(uint32_t a, uint32_t b, uint32_t c) {
    TSched s; s.a = a; s.b = b; s.c = c;
    s.c1 = c + 1u; s.a2 = a + 2u; s.b3 = b + 3u; s.c4 = c + 4u; s.a5 = a + 5u;
    return s;
}

#define TFF_ROUND(x0, x1, r) { x0 = addf(x0, x1, one); x1 = __funnelshift_l(x1, x1, (r)); x1 ^= x0; }
#define TFF_ROUNDM(x0, x1, POW) { x0 = addf(x0, x1, one); x1 = rotm_xor(x1, POW, x0); }

#define TFF_R4A(x0, x1) { TFF_ROUNDM(x0,x1,p13) TFF_ROUND(x0,x1,15) TFF_ROUND(x0,x1,26) TFF_ROUND(x0,x1,6) }
#define TFF_R4B(x0, x1) { TFF_ROUNDM(x0,x1,p17) TFF_ROUND(x0,x1,29) TFF_ROUND(x0,x1,16) TFF_ROUND(x0,x1,24) }

// threefry2x32 at counter (0, idx): alu = 15 SHF + 20 LOP3 + 1 XOR,
// imad = 31 adds + 5 wide-muls.
__device__ __forceinline__ uint32_t tff_bits(const TSched k, uint32_t idx,
                                             uint32_t one, uint32_t p13, uint32_t p17) {
    uint32_t x0 = k.a, x1 = addf(idx, k.b, one);
    TFF_R4A(x0, x1); x0 = addf(x0, k.b, one); x1 = addf(x1, k.c1, one);
    TFF_R4B(x0, x1); x0 = addf(x0, k.c, one); x1 = addf(x1, k.a2, one);
    TFF_R4A(x0, x1); x0 = addf(x0, k.a, one); x1 = addf(x1, k.b3, one);
    TFF_R4B(x0, x1); x0 = addf(x0, k.b, one); x1 = addf(x1, k.c4, one);
    TFF_R4A(x0, x1); x0 = addf(x0, k.c, one); x1 = addf(x1, k.a5, one);
    return x0 ^ x1;
}

// Pre-shifted threshold: uniform(bits) < e  <=>  bits < (ceil(e*2^23) << 9).
__device__ __forceinline__ uint32_t thresh_shifted(float e) {
    return ((uint32_t)ceil((double)e * 8388608.0)) << 9;
}

// ============================================================================
// Per-channel key cache (keys depend only on channel c).
// ============================================================================

__device__ uint32_t g_keys[4][16];

__global__ void key_setup_kernel() {
    const int c = threadIdx.x;
    if (c >= 4) return;
    uint32_t t0, t1;
    const TKey root = mk_key(0u, 42u);
    tf_pair(root, 0u, (uint32_t)c, t0, t1);
    const TKey kc = mk_key(t0, t1);

    tf_pair(kc, 0u, 0u, t0, t1); const TKey s1 = mk_key(t0, t1);
    tf_pair(kc, 0u, 1u, t0, t1); const TKey s2 = mk_key(t0, t1);
    tf_pair(kc, 0u, 2u, t0, t1); const TKey s3 = mk_key(t0, t1);

    tf_pair(s1, 0u, 0u, t0, t1); const TKey sub_a = mk_key(t0, t1);
    tf_pair(sub_a, 0u, 1u, t0, t1); const TKey k_subdata = mk_key(t0, t1);
    tf_pair(s1, 0u, 1u, t0, t1); const TKey k_submask = mk_key(t0, t1);

    tf_pair(s3, 0u, 0u, t0, t1); const TKey k_insflag = mk_key(t0, t1);
    tf_pair(s3, 0u, 1u, t0, t1); const TKey ins_b = mk_key(t0, t1);
    tf_pair(ins_b, 0u, 1u, t0, t1); const TKey k_inssym = mk_key(t0, t1);

    uint32_t* kp = g_keys[c];
    kp[0] = k_submask.a; kp[1] = k_submask.b; kp[2] = k_submask.c;
    kp[3] = s2.a;        kp[4] = s2.b;        kp[5] = s2.c;
    kp[6] = k_subdata.a; kp[7] = k_subdata.b; kp[8] = k_subdata.c;
    kp[9] = k_insflag.a; kp[10] = k_insflag.b; kp[11] = k_insflag.c;
    kp[12] = k_inssym.a; kp[13] = k_inssym.b; kp[14] = k_inssym.c;
}

// ============================================================================
// Warp-per-(row, channel); lane owns 16 contiguous elements.
// ============================================================================

__global__ void __launch_bounds__(256, 5)
channel_warp_kernel(const float* __restrict__ x, float* __restrict__ out, int B) {
    const int gw = (int)((blockIdx.x * blockDim.x + threadIdx.x) >> 5);
    const int lane = threadIdx.x & 31;
    if (gw >= B * 4) return;
    const int c = gw & 3;
    const int b = gw >> 2;

    const uint32_t KsubS = thresh_shifted(0.02f);
    const uint32_t KdelS = thresh_shifted(0.01f);
    const uint32_t KinsS = thresh_shifted(0.01f);

    const uint32_t* kp = g_keys[c];
    const uint32_t one = (kp[0] >> 31) | 1u;       // opaque runtime 1
    const uint32_t p13 = (1u << 13) * one;         // opaque 2^13
    const uint32_t p17 = (1u << 17) * one;         // opaque 2^17
    const TSched kSubM = mk_sched(kp[0], kp[1], kp[2]);
    const TSched kDel  = mk_sched(kp[3], kp[4], kp[5]);

    // ---- load my 16 elements, +1.0f folded in (mod threshold becomes 5)
    float v[16];
    const float4* __restrict__ xr4 =
        (const float4*)(x + (size_t)b * 512 + (size_t)lane * 16);
    #pragma unroll
    for (int q = 0; q < 4; q++) {
        const float4 f = xr4[q];
        v[q * 4 + 0] = f.x + 1.0f; v[q * 4 + 1] = f.y + 1.0f;
        v[q * 4 + 2] = f.z + 1.0f; v[q * 4 + 3] = f.w + 1.0f;
    }

    // ---- phase 1: sub-need + keep flags (unroll 4, ILP=8)
    const uint32_t base = (uint32_t)b * 512u + (uint32_t)lane * 16u;
    uint32_t keepmask = 0u, subneed = 0u;
    {
        uint32_t bit = 1u;
        #pragma unroll 4
        for (int i = 0; i < 16; i++) {
            const uint32_t idx = base + (uint32_t)i;
            const uint32_t bs = tff_bits(kSubM, idx, one, p13, p17);
            const uint32_t bd = tff_bits(kDel,  idx, one, p13, p17);
            if (bs < KsubS)  subneed  |= bit;
            if (bd >= KdelS) keepmask |= bit;
            bit <<= 1;
        }
    }

    // ---- deferred sub draws: per-lane bit loop, 2-bit packed deltas
    uint32_t subdelta = 0u;
    {
        const TSched kSubD = mk_sched(kp[6], kp[7], kp[8]);
        uint32_t m = subneed;
        while (m) {
            const int i = __ffs(m) - 1; m &= m - 1u;
            const uint32_t db = tff_bits(kSubD, base + (uint32_t)i, one, p13, p17);
            subdelta |= (db & 3u) << (2 * i);
        }
    }

    // ---- scan 1: exclusive scan of keep counts -> compacted offset
    const int kn = __popc(keepmask);
    int incl = kn;
    #pragma unroll
    for (int d = 1; d < 32; d <<= 1) {
        const int nv = __shfl_up_sync(FULLM, incl, d);
        if (lane >= d) incl += nv;
    }
    const int ofs = incl - kn;

    // ---- phase 2: ins flags at compacted indices (iterative j, unroll 4)
    const uint32_t insbase = (uint32_t)b * 514u;
    uint32_t insmask = 0u;
    {
        const TSched kInsF = mk_sched(kp[9], kp[10], kp[11]);
        uint32_t km = keepmask, bit = 1u;
        uint32_t j = insbase + (uint32_t)ofs;
        #pragma unroll 4
        for (int i = 0; i < 16; i++) {
            const uint32_t bi = tff_bits(kInsF, j, one, p13, p17);
            if (bi < KinsS) insmask |= bit;
            j += km & 1u; km >>= 1; bit <<= 1;
        }
    }
    insmask &= keepmask;

    // ---- scan 2: output offsets
    const int myout = kn + __popc(insmask);
    int incl2 = myout;
    #pragma unroll
    for (int d = 1; d < 32; d <<= 1) {
        const int nv = __shfl_up_sync(FULLM, incl2, d);
        if (lane >= d) incl2 += nv;
    }
    const int outofs = incl2 - myout;
    const int total_out = __shfl_sync(FULLM, incl2, 31);

    float* __restrict__ orow = out + ((size_t)b * 4 + (size_t)c) * 514;

    // ---- write kept elements: full unroll (static v[i]), branch-free positions
    #pragma unroll
    for (int i = 0; i < 16; i++) {
        const uint32_t below = (1u << i) - 1u;
        const int pos = outofs + __popc(keepmask & below) + __popc(insmask & below);
        float vv = v[i] + (float)((subdelta >> (2 * i)) & 3u);   // in [1,7]
        if (vv >= 5.0f) vv -= 4.0f;                               // exact mod-4 (+1 folded)
        if (((keepmask >> i) & 1u) && pos < 514) orow[pos] = vv;
    }

    // ---- inserted symbols: rare per-lane bit loop
    {
        const TSched kInsS2 = mk_sched(kp[12], kp[13], kp[14]);
        uint32_t m = insmask;
        while (m) {
            const int i = __ffs(m) - 1; m &= m - 1u;
            const uint32_t below = (1u << i) - 1u;
            const int nk = __popc(keepmask & below);
            const uint32_t j = insbase + (uint32_t)(ofs + nk);
            const int pos = outofs + nk + __popc(insmask & below) + 1;
            const uint32_t sb = tff_bits(kInsS2, j, one, p13, p17);
            if (pos < 514) orow[pos] = (float)(sb & 3u) + 1.0f;
        }
    }

    // ---- tail padding: 0.0 (= -1 + 1)
    for (int p = total_out + lane; p < 514; p += 32) orow[p] = 0.0f;
}

extern "C" void kernel_launch(void* const* d_in, const int* in_sizes, int n_in,
                              void* d_out, int out_size) {
    const float* x = (const float*)d_in[0];   // segment_en [B, 512]
    float* out = (float*)d_out;               // [B, 4, 514] float32
    const int B = in_sizes[0] / 512;

    key_setup_kernel<<<1, 4>>>();

    const long long total_threads = (long long)B * 4 * 32;
    const int block = 256;
    const int grid = (int)((total_threads + block - 1) / block);
    channel_warp_kernel<<<grid, block>>>(x, out, B);
}

// round 12
// speedup vs baseline: 1.0402x; 1.0390x over previous
#include <cuda_runtime.h>
#include <cstdint>

// ============================================================================
// Bit-exact JAX threefry2x32 (partitionable) — rel_err = 0.0 verified R2-R11.
// R12 = R9 (best structure: SHF rotates + mad-forced adds, unroll-4, occ 59%)
//     + epilogue alu trims: iterative write-position accumulator (replaces
//       per-element dual-popc), minor dead-op removal. alu pipe at 92.5% is
//       the binder; deleted alu ops convert ~1:1 to time.
// (mul.wide rotate conversion falsified at BOTH occ 47% and 59% — reverted.)
// ============================================================================

#define FULLM 0xffffffffu

struct TKey { uint32_t a, b, c; };

__device__ __forceinline__ TKey mk_key(uint32_t k0, uint32_t k1) {
    TKey k; k.a = k0; k.b = k1; k.c = k0 ^ k1 ^ 0x1BD11BDAu; return k;
}

// ---- plain threefry (setup kernel only)
#define TF_ROUND(x0, x1, r) { x0 += x1; x1 = __funnelshift_l(x1, x1, (r)); x1 ^= x0; }
#define TF_R4A(x0, x1) { TF_ROUND(x0,x1,13) TF_ROUND(x0,x1,15) TF_ROUND(x0,x1,26) TF_ROUND(x0,x1,6) }
#define TF_R4B(x0, x1) { TF_ROUND(x0,x1,17) TF_ROUND(x0,x1,29) TF_ROUND(x0,x1,16) TF_ROUND(x0,x1,24) }

__device__ __forceinline__ void tf_pair(const TKey k, uint32_t c0, uint32_t c1,
                                        uint32_t& o0, uint32_t& o1) {
    uint32_t x0 = c0 + k.a, x1 = c1 + k.b;
    TF_R4A(x0, x1); x0 += k.b; x1 += k.c + 1u;
    TF_R4B(x0, x1); x0 += k.c; x1 += k.a + 2u;
    TF_R4A(x0, x1); x0 += k.a; x1 += k.b + 3u;
    TF_R4B(x0, x1); x0 += k.b; x1 += k.c + 4u;
    TF_R4A(x0, x1); x0 += k.c; x1 += k.a + 5u;
    o0 = x0; o1 = x1;
}

// ---- add on the IMAD pipe (`one` = opaque runtime 1; keeps the 31 adds/tf
// off the saturated alu pipe — R5/R9-verified)
__device__ __forceinline__ uint32_t addf(uint32_t a, uint32_t b, uint32_t one) {
    uint32_t d;
    asm("mad.lo.u32 %0, %1, %2, %3;" : "=r"(d) : "r"(a), "r"(one), "r"(b));
    return d;
}

struct TSched {
    uint32_t a, b, c;
    uint32_t c1, a2, b3, c4, a5;   // k.c+1, k.a+2, k.b+3, k.c+4, k.a+5
};

__device__ __forceinline__ TSched mk_sched(uint32_t a, uint32_t b, uint32_t c) {
    TSched s; s.a = a; s.b = b; s.c = c;
    s.c1 = c + 1u; s.a2 = a + 2u; s.b3 = b + 3u; s.c4 = c + 4u; s.a5 = a + 5u;
    return s;
}

#define TFF_ROUND(x0, x1, r) { x0 = addf(x0, x1, one); x1 = __funnelshift_l(x1, x1, (r)); x1 ^= x0; }
#define TFF_R4A(x0, x1) { TFF_ROUND(x0,x1,13) TFF_ROUND(x0,x1,15) TFF_ROUND(x0,x1,26) TFF_ROUND(x0,x1,6) }
#define TFF_R4B(x0, x1) { TFF_ROUND(x0,x1,17) TFF_ROUND(x0,x1,29) TFF_ROUND(x0,x1,16) TFF_ROUND(x0,x1,24) }

// threefry2x32 at counter (0, idx): 20 SHF + 21 LOP3 (alu), 31 IMAD (fma)
__device__ __forceinline__ uint32_t tff_bits(const TSched k, uint32_t idx, uint32_t one) {
    uint32_t x0 = k.a, x1 = addf(idx, k.b, one);
    TFF_R4A(x0, x1); x0 = addf(x0, k.b, one); x1 = addf(x1, k.c1, one);
    TFF_R4B(x0, x1); x0 = addf(x0, k.c, one); x1 = addf(x1, k.a2, one);
    TFF_R4A(x0, x1); x0 = addf(x0, k.a, one); x1 = addf(x1, k.b3, one);
    TFF_R4B(x0, x1); x0 = addf(x0, k.b, one); x1 = addf(x1, k.c4, one);
    TFF_R4A(x0, x1); x0 = addf(x0, k.c, one); x1 = addf(x1, k.a5, one);
    return x0 ^ x1;
}

// Pre-shifted threshold: uniform(bits) < e  <=>  bits < (ceil(e*2^23) << 9).
__device__ __forceinline__ uint32_t thresh_shifted(float e) {
    return ((uint32_t)ceil((double)e * 8388608.0)) << 9;
}

// ============================================================================
// Per-channel key cache (keys depend only on channel c).
// ============================================================================

__device__ uint32_t g_keys[4][16];

__global__ void key_setup_kernel() {
    const int c = threadIdx.x;
    if (c >= 4) return;
    uint32_t t0, t1;
    const TKey root = mk_key(0u, 42u);
    tf_pair(root, 0u, (uint32_t)c, t0, t1);
    const TKey kc = mk_key(t0, t1);

    tf_pair(kc, 0u, 0u, t0, t1); const TKey s1 = mk_key(t0, t1);
    tf_pair(kc, 0u, 1u, t0, t1); const TKey s2 = mk_key(t0, t1);
    tf_pair(kc, 0u, 2u, t0, t1); const TKey s3 = mk_key(t0, t1);

    tf_pair(s1, 0u, 0u, t0, t1); const TKey sub_a = mk_key(t0, t1);
    tf_pair(sub_a, 0u, 1u, t0, t1); const TKey k_subdata = mk_key(t0, t1);
    tf_pair(s1, 0u, 1u, t0, t1); const TKey k_submask = mk_key(t0, t1);

    tf_pair(s3, 0u, 0u, t0, t1); const TKey k_insflag = mk_key(t0, t1);
    tf_pair(s3, 0u, 1u, t0, t1); const TKey ins_b = mk_key(t0, t1);
    tf_pair(ins_b, 0u, 1u, t0, t1); const TKey k_inssym = mk_key(t0, t1);

    uint32_t* kp = g_keys[c];
    kp[0] = k_submask.a; kp[1] = k_submask.b; kp[2] = k_submask.c;
    kp[3] = s2.a;        kp[4] = s2.b;        kp[5] = s2.c;
    kp[6] = k_subdata.a; kp[7] = k_subdata.b; kp[8] = k_subdata.c;
    kp[9] = k_insflag.a; kp[10] = k_insflag.b; kp[11] = k_insflag.c;
    kp[12] = k_inssym.a; kp[13] = k_inssym.b; kp[14] = k_inssym.c;
}

// ============================================================================
// Warp-per-(row, channel); lane owns 16 contiguous elements.
// ============================================================================

__global__ void __launch_bounds__(256)
channel_warp_kernel(const float* __restrict__ x, float* __restrict__ out, int B) {
    const int gw = (int)((blockIdx.x * blockDim.x + threadIdx.x) >> 5);
    const int lane = threadIdx.x & 31;
    if (gw >= B * 4) return;
    const int c = gw & 3;
    const int b = gw >> 2;

    const uint32_t KsubS = thresh_shifted(0.02f);
    const uint32_t KdelS = thresh_shifted(0.01f);
    const uint32_t KinsS = thresh_shifted(0.01f);

    const uint32_t* kp = g_keys[c];
    const uint32_t one = (kp[0] >> 31) | 1u;       // opaque runtime 1
    const TSched kSubM = mk_sched(kp[0], kp[1], kp[2]);
    const TSched kDel  = mk_sched(kp[3], kp[4], kp[5]);

    // ---- load my 16 elements, +1.0f folded in (mod threshold becomes 5)
    float v[16];
    const float4* __restrict__ xr4 =
        (const float4*)(x + (size_t)b * 512 + (size_t)lane * 16);
    #pragma unroll
    for (int q = 0; q < 4; q++) {
        const float4 f = xr4[q];
        v[q * 4 + 0] = f.x + 1.0f; v[q * 4 + 1] = f.y + 1.0f;
        v[q * 4 + 2] = f.z + 1.0f; v[q * 4 + 3] = f.w + 1.0f;
    }

    // ---- phase 1: sub-need + keep flags (unroll 4, ILP=8)
    const uint32_t base = (uint32_t)b * 512u + (uint32_t)lane * 16u;
    uint32_t keepmask = 0u, subneed = 0u;
    {
        uint32_t bit = 1u;
        #pragma unroll 4
        for (int i = 0; i < 16; i++) {
            const uint32_t idx = base + (uint32_t)i;
            const uint32_t bs = tff_bits(kSubM, idx, one);
            const uint32_t bd = tff_bits(kDel,  idx, one);
            if (bs < KsubS)  subneed  |= bit;
            if (bd >= KdelS) keepmask |= bit;
            bit <<= 1;
        }
    }

    // ---- deferred sub draws: per-lane bit loop, 2-bit packed deltas
    uint32_t subdelta = 0u;
    {
        const TSched kSubD = mk_sched(kp[6], kp[7], kp[8]);
        uint32_t m = subneed;
        while (m) {
            const int i = __ffs(m) - 1; m &= m - 1u;
            const uint32_t db = tff_bits(kSubD, base + (uint32_t)i, one);
            subdelta |= (db & 3u) << (2 * i);
        }
    }

    // ---- scan 1: exclusive scan of keep counts -> compacted offset
    const int kn = __popc(keepmask);
    int incl = kn;
    #pragma unroll
    for (int d = 1; d < 32; d <<= 1) {
        const int nv = __shfl_up_sync(FULLM, incl, d);
        if (lane >= d) incl += nv;
    }
    const int ofs = incl - kn;

    // ---- phase 2: ins flags at compacted indices (iterative j, unroll 4)
    const uint32_t insbase = (uint32_t)b * 514u;
    uint32_t insmask = 0u;
    {
        const TSched kInsF = mk_sched(kp[9], kp[10], kp[11]);
        uint32_t km = keepmask, bit = 1u;
        uint32_t j = insbase + (uint32_t)ofs;
        #pragma unroll 4
        for (int i = 0; i < 16; i++) {
            const uint32_t bi = tff_bits(kInsF, j, one);
            if (bi < KinsS) insmask |= bit;
            j += km & 1u; km >>= 1; bit <<= 1;
        }
    }
    insmask &= keepmask;

    // ---- scan 2: output offsets
    const int myout = kn + __popc(insmask);
    int incl2 = myout;
    #pragma unroll
    for (int d = 1; d < 32; d <<= 1) {
        const int nv = __shfl_up_sync(FULLM, incl2, d);
        if (lane >= d) incl2 += nv;
    }
    const int outofs = incl2 - myout;
    const int total_out = __shfl_sync(FULLM, incl2, 31);

    float* __restrict__ orow = out + ((size_t)b * 4 + (size_t)c) * 514;

    // ---- write kept elements: iterative position accumulator (replaces
    // per-element dual-popc: 6 alu -> 3 alu per element)
    {
        int pos = outofs;
        uint32_t km = keepmask, im = insmask, sd = subdelta;
        #pragma unroll
        for (int i = 0; i < 16; i++) {
            float vv = v[i] + (float)(sd & 3u);       // in [1,7]
            if (vv >= 5.0f) vv -= 4.0f;               // exact mod-4 (+1 folded)
            if ((km & 1u) && pos < 514) orow[pos] = vv;
            pos += (int)(km & 1u) + (int)(im & 1u);
            km >>= 1; im >>= 1; sd >>= 2;
        }
    }

    // ---- inserted symbols: rare per-lane bit loop
    {
        const TSched kInsS2 = mk_sched(kp[12], kp[13], kp[14]);
        uint32_t m = insmask;
        while (m) {
            const int i = __ffs(m) - 1; m &= m - 1u;
            const uint32_t below = (1u << i) - 1u;
            const int nk = __popc(keepmask & below);
            const uint32_t j = insbase + (uint32_t)(ofs + nk);
            const int pos = outofs + nk + __popc(insmask & below) + 1;
            const uint32_t sb = tff_bits(kInsS2, j, one);
            if (pos < 514) orow[pos] = (float)(sb & 3u) + 1.0f;
        }
    }

    // ---- tail padding: 0.0 (= -1 + 1)
    for (int p = total_out + lane; p < 514; p += 32) orow[p] = 0.0f;
}

extern "C" void kernel_launch(void* const* d_in, const int* in_sizes, int n_in,
                              void* d_out, int out_size) {
    const float* x = (const float*)d_in[0];   // segment_en [B, 512]
    float* out = (float*)d_out;               // [B, 4, 514] float32
    const int B = in_sizes[0] / 512;

    key_setup_kernel<<<1, 4>>>();

    const long long total_threads = (long long)B * 4 * 32;
    const int block = 256;
    const int grid = (int)((total_threads + block - 1) / block);
    channel_warp_kernel<<<grid, block>>>(x, out, B);
}

// round 13
// speedup vs baseline: 1.0523x; 1.0117x over previous
#include <cuda_runtime.h>
#include <cstdint>

// ============================================================================
// Bit-exact JAX threefry2x32 (partitionable) — rel_err = 0.0 verified R2-R12.
// R13 = R12 base with two issued-count-neutral scheduling changes:
//   (1) input float4 loads moved AFTER phase 2 (kill MLP_p1=4 front-batch;
//       L1tex-queue cross-CTA spread model, B300_MICROARCH) — loads hide
//       behind ~2300 ALU ops instead of stalling the warp front.
//   (2) block 256 -> 128 (same occ at 48 regs; finer wave balance).
// ============================================================================

#define FULLM 0xffffffffu

struct TKey { uint32_t a, b, c; };

__device__ __forceinline__ TKey mk_key(uint32_t k0, uint32_t k1) {
    TKey k; k.a = k0; k.b = k1; k.c = k0 ^ k1 ^ 0x1BD11BDAu; return k;
}

// ---- plain threefry (setup kernel only)
#define TF_ROUND(x0, x1, r) { x0 += x1; x1 = __funnelshift_l(x1, x1, (r)); x1 ^= x0; }
#define TF_R4A(x0, x1) { TF_ROUND(x0,x1,13) TF_ROUND(x0,x1,15) TF_ROUND(x0,x1,26) TF_ROUND(x0,x1,6) }
#define TF_R4B(x0, x1) { TF_ROUND(x0,x1,17) TF_ROUND(x0,x1,29) TF_ROUND(x0,x1,16) TF_ROUND(x0,x1,24) }

__device__ __forceinline__ void tf_pair(const TKey k, uint32_t c0, uint32_t c1,
                                        uint32_t& o0, uint32_t& o1) {
    uint32_t x0 = c0 + k.a, x1 = c1 + k.b;
    TF_R4A(x0, x1); x0 += k.b; x1 += k.c + 1u;
    TF_R4B(x0, x1); x0 += k.c; x1 += k.a + 2u;
    TF_R4A(x0, x1); x0 += k.a; x1 += k.b + 3u;
    TF_R4B(x0, x1); x0 += k.b; x1 += k.c + 4u;
    TF_R4A(x0, x1); x0 += k.c; x1 += k.a + 5u;
    o0 = x0; o1 = x1;
}

// ---- add on the IMAD pipe (`one` = opaque runtime 1)
__device__ __forceinline__ uint32_t addf(uint32_t a, uint32_t b, uint32_t one) {
    uint32_t d;
    asm("mad.lo.u32 %0, %1, %2, %3;" : "=r"(d) : "r"(a), "r"(one), "r"(b));
    return d;
}

struct TSched {
    uint32_t a, b, c;
    uint32_t c1, a2, b3, c4, a5;   // k.c+1, k.a+2, k.b+3, k.c+4, k.a+5
};

__device__ __forceinline__ TSched mk_sched(uint32_t a, uint32_t b, uint32_t c) {
    TSched s; s.a = a; s.b = b; s.c = c;
    s.c1 = c + 1u; s.a2 = a + 2u; s.b3 = b + 3u; s.c4 = c + 4u; s.a5 = a + 5u;
    return s;
}

#define TFF_ROUND(x0, x1, r) { x0 = addf(x0, x1, one); x1 = __funnelshift_l(x1, x1, (r)); x1 ^= x0; }
#define TFF_R4A(x0, x1) { TFF_ROUND(x0,x1,13) TFF_ROUND(x0,x1,15) TFF_ROUND(x0,x1,26) TFF_ROUND(x0,x1,6) }
#define TFF_R4B(x0, x1) { TFF_ROUND(x0,x1,17) TFF_ROUND(x0,x1,29) TFF_ROUND(x0,x1,16) TFF_ROUND(x0,x1,24) }

// threefry2x32 at counter (0, idx): 20 SHF + 21 LOP3 (alu), 31 IMAD
__device__ __forceinline__ uint32_t tff_bits(const TSched k, uint32_t idx, uint32_t one) {
    uint32_t x0 = k.a, x1 = addf(idx, k.b, one);
    TFF_R4A(x0, x1); x0 = addf(x0, k.b, one); x1 = addf(x1, k.c1, one);
    TFF_R4B(x0, x1); x0 = addf(x0, k.c, one); x1 = addf(x1, k.a2, one);
    TFF_R4A(x0, x1); x0 = addf(x0, k.a, one); x1 = addf(x1, k.b3, one);
    TFF_R4B(x0, x1); x0 = addf(x0, k.b, one); x1 = addf(x1, k.c4, one);
    TFF_R4A(x0, x1); x0 = addf(x0, k.c, one); x1 = addf(x1, k.a5, one);
    return x0 ^ x1;
}

// Pre-shifted threshold: uniform(bits) < e  <=>  bits < (ceil(e*2^23) << 9).
__device__ __forceinline__ uint32_t thresh_shifted(float e) {
    return ((uint32_t)ceil((double)e * 8388608.0)) << 9;
}

// ============================================================================
// Per-channel key cache (keys depend only on channel c).
// ============================================================================

__device__ uint32_t g_keys[4][16];

__global__ void key_setup_kernel() {
    const int c = threadIdx.x;
    if (c >= 4) return;
    uint32_t t0, t1;
    const TKey root = mk_key(0u, 42u);
    tf_pair(root, 0u, (uint32_t)c, t0, t1);
    const TKey kc = mk_key(t0, t1);

    tf_pair(kc, 0u, 0u, t0, t1); const TKey s1 = mk_key(t0, t1);
    tf_pair(kc, 0u, 1u, t0, t1); const TKey s2 = mk_key(t0, t1);
    tf_pair(kc, 0u, 2u, t0, t1); const TKey s3 = mk_key(t0, t1);

    tf_pair(s1, 0u, 0u, t0, t1); const TKey sub_a = mk_key(t0, t1);
    tf_pair(sub_a, 0u, 1u, t0, t1); const TKey k_subdata = mk_key(t0, t1);
    tf_pair(s1, 0u, 1u, t0, t1); const TKey k_submask = mk_key(t0, t1);

    tf_pair(s3, 0u, 0u, t0, t1); const TKey k_insflag = mk_key(t0, t1);
    tf_pair(s3, 0u, 1u, t0, t1); const TKey ins_b = mk_key(t0, t1);
    tf_pair(ins_b, 0u, 1u, t0, t1); const TKey k_inssym = mk_key(t0, t1);

    uint32_t* kp = g_keys[c];
    kp[0] = k_submask.a; kp[1] = k_submask.b; kp[2] = k_submask.c;
    kp[3] = s2.a;        kp[4] = s2.b;        kp[5] = s2.c;
    kp[6] = k_subdata.a; kp[7] = k_subdata.b; kp[8] = k_subdata.c;
    kp[9] = k_insflag.a; kp[10] = k_insflag.b; kp[11] = k_insflag.c;
    kp[12] = k_inssym.a; kp[13] = k_inssym.b; kp[14] = k_inssym.c;
}

// ============================================================================
// Warp-per-(row, channel); lane owns 16 contiguous elements.
// ============================================================================

__global__ void __launch_bounds__(128)
channel_warp_kernel(const float* __restrict__ x, float* __restrict__ out, int B) {
    const int gw = (int)((blockIdx.x * blockDim.x + threadIdx.x) >> 5);
    const int lane = threadIdx.x & 31;
    if (gw >= B * 4) return;
    const int c = gw & 3;
    const int b = gw >> 2;

    const uint32_t KsubS = thresh_shifted(0.02f);
    const uint32_t KdelS = thresh_shifted(0.01f);
    const uint32_t KinsS = thresh_shifted(0.01f);

    const uint32_t* kp = g_keys[c];
    const uint32_t one = (kp[0] >> 31) | 1u;       // opaque runtime 1
    const TSched kSubM = mk_sched(kp[0], kp[1], kp[2]);
    const TSched kDel  = mk_sched(kp[3], kp[4], kp[5]);

    // ---- phase 1: sub-need + keep flags (unroll 4, ILP=8). Input NOT loaded
    // yet: no front-batched LDGs -> no cross-CTA L1tex-queue spread.
    const uint32_t base = (uint32_t)b * 512u + (uint32_t)lane * 16u;
    uint32_t keepmask = 0u, subneed = 0u;
    {
        uint32_t bit = 1u;
        #pragma unroll 4
        for (int i = 0; i < 16; i++) {
            const uint32_t idx = base + (uint32_t)i;
            const uint32_t bs = tff_bits(kSubM, idx, one);
            const uint32_t bd = tff_bits(kDel,  idx, one);
            if (bs < KsubS)  subneed  |= bit;
            if (bd >= KdelS) keepmask |= bit;
            bit <<= 1;
        }
    }

    // ---- kick off the input loads NOW: their ~600cyc DRAM/L2 latency hides
    // behind phase 2's 16 more threefry chains (~1200 cyc of ALU).
    float v[16];
    {
        const float4* __restrict__ xr4 =
            (const float4*)(x + (size_t)b * 512 + (size_t)lane * 16);
        #pragma unroll
        for (int q = 0; q < 4; q++) {
            const float4 f = xr4[q];
            v[q * 4 + 0] = f.x + 1.0f; v[q * 4 + 1] = f.y + 1.0f;
            v[q * 4 + 2] = f.z + 1.0f; v[q * 4 + 3] = f.w + 1.0f;
        }
    }

    // ---- deferred sub draws: per-lane bit loop, 2-bit packed deltas
    uint32_t subdelta = 0u;
    {
        const TSched kSubD = mk_sched(kp[6], kp[7], kp[8]);
        uint32_t m = subneed;
        while (m) {
            const int i = __ffs(m) - 1; m &= m - 1u;
            const uint32_t db = tff_bits(kSubD, base + (uint32_t)i, one);
            subdelta |= (db & 3u) << (2 * i);
        }
    }

    // ---- scan 1: exclusive scan of keep counts -> compacted offset
    const int kn = __popc(keepmask);
    int incl = kn;
    #pragma unroll
    for (int d = 1; d < 32; d <<= 1) {
        const int nv = __shfl_up_sync(FULLM, incl, d);
        if (lane >= d) incl += nv;
    }
    const int ofs = incl - kn;

    // ---- phase 2: ins flags at compacted indices (iterative j, unroll 4)
    const uint32_t insbase = (uint32_t)b * 514u;
    uint32_t insmask = 0u;
    {
        const TSched kInsF = mk_sched(kp[9], kp[10], kp[11]);
        uint32_t km = keepmask, bit = 1u;
        uint32_t j = insbase + (uint32_t)ofs;
        #pragma unroll 4
        for (int i = 0; i < 16; i++) {
            const uint32_t bi = tff_bits(kInsF, j, one);
            if (bi < KinsS) insmask |= bit;
            j += km & 1u; km >>= 1; bit <<= 1;
        }
    }
    insmask &= keepmask;

    // ---- scan 2: output offsets
    const int myout = kn + __popc(insmask);
    int incl2 = myout;
    #pragma unroll
    for (int d = 1; d < 32; d <<= 1) {
        const int nv = __shfl_up_sync(FULLM, incl2, d);
        if (lane >= d) incl2 += nv;
    }
    const int outofs = incl2 - myout;
    const int total_out = __shfl_sync(FULLM, incl2, 31);

    float* __restrict__ orow = out + ((size_t)b * 4 + (size_t)c) * 514;

    // ---- write kept elements: iterative position accumulator
    {
        int pos = outofs;
        uint32_t km = keepmask, im = insmask, sd = subdelta;
        #pragma unroll
        for (int i = 0; i < 16; i++) {
            float vv = v[i] + (float)(sd & 3u);       // in [1,7]
            if (vv >= 5.0f) vv -= 4.0f;               // exact mod-4 (+1 folded)
            if ((km & 1u) && pos < 514) orow[pos] = vv;
            pos += (int)(km & 1u) + (int)(im & 1u);
            km >>= 1; im >>= 1; sd >>= 2;
        }
    }

    // ---- inserted symbols: rare per-lane bit loop
    {
        const TSched kInsS2 = mk_sched(kp[12], kp[13], kp[14]);
        uint32_t m = insmask;
        while (m) {
            const int i = __ffs(m) - 1; m &= m - 1u;
            const uint32_t below = (1u << i) - 1u;
            const int nk = __popc(keepmask & below);
            const uint32_t j = insbase + (uint32_t)(ofs + nk);
            const int pos = outofs + nk + __popc(insmask & below) + 1;
            const uint32_t sb = tff_bits(kInsS2, j, one);
            if (pos < 514) orow[pos] = (float)(sb & 3u) + 1.0f;
        }
    }

    // ---- tail padding: 0.0 (= -1 + 1)
    for (int p = total_out + lane; p < 514; p += 32) orow[p] = 0.0f;
}

extern "C" void kernel_launch(void* const* d_in, const int* in_sizes, int n_in,
                              void* d_out, int out_size) {
    const float* x = (const float*)d_in[0];   // segment_en [B, 512]
    float* out = (float*)d_out;               // [B, 4, 514] float32
    const int B = in_sizes[0] / 512;

    key_setup_kernel<<<1, 4>>>();

    const long long total_threads = (long long)B * 4 * 32;
    const int block = 128;
    const int grid = (int)((total_threads + block - 1) / block);
    channel_warp_kernel<<<grid, block>>>(x, out, B);
}

// round 14
// speedup vs baseline: 1.0598x; 1.0071x over previous
#include <cuda_runtime.h>
#include <cstdint>

// ============================================================================
// Bit-exact JAX threefry2x32 (partitionable) — rel_err = 0.0 verified R2-R13.
// R14 = R13 (best: 326.0us, alu 94.2% saturated, occ 59%) + alu-neutral 2-bit
//   value pack: F2I+IMAD pack (fma pipe), SWAR mod-4 sub-apply (4 LOP3 once),
//   I2F+FADD write (fma pipe). -15 live regs -> occ ~87% to close the last
//   scheduling gap. (R7's pack failed because its cost landed on alu at
//   pinned occupancy; this lands on the 24%-idle fma pipe and unpins occ.)
// ============================================================================

#define FULLM 0xffffffffu

struct TKey { uint32_t a, b, c; };

__device__ __forceinline__ TKey mk_key(uint32_t k0, uint32_t k1) {
    TKey k; k.a = k0; k.b = k1; k.c = k0 ^ k1 ^ 0x1BD11BDAu; return k;
}

// ---- plain threefry (setup kernel only)
#define TF_ROUND(x0, x1, r) { x0 += x1; x1 = __funnelshift_l(x1, x1, (r)); x1 ^= x0; }
#define TF_R4A(x0, x1) { TF_ROUND(x0,x1,13) TF_ROUND(x0,x1,15) TF_ROUND(x0,x1,26) TF_ROUND(x0,x1,6) }
#define TF_R4B(x0, x1) { TF_ROUND(x0,x1,17) TF_ROUND(x0,x1,29) TF_ROUND(x0,x1,16) TF_ROUND(x0,x1,24) }

__device__ __forceinline__ void tf_pair(const TKey k, uint32_t c0, uint32_t c1,
                                        uint32_t& o0, uint32_t& o1) {
    uint32_t x0 = c0 + k.a, x1 = c1 + k.b;
    TF_R4A(x0, x1); x0 += k.b; x1 += k.c + 1u;
    TF_R4B(x0, x1); x0 += k.c; x1 += k.a + 2u;
    TF_R4A(x0, x1); x0 += k.a; x1 += k.b + 3u;
    TF_R4B(x0, x1); x0 += k.b; x1 += k.c + 4u;
    TF_R4A(x0, x1); x0 += k.c; x1 += k.a + 5u;
    o0 = x0; o1 = x1;
}

// ---- add on the IMAD pipe (`one` = opaque runtime 1)
__device__ __forceinline__ uint32_t addf(uint32_t a, uint32_t b, uint32_t one) {
    uint32_t d;
    asm("mad.lo.u32 %0, %1, %2, %3;" : "=r"(d) : "r"(a), "r"(one), "r"(b));
    return d;
}

// ---- shift-and-accumulate on the IMAD pipe: d = a * mult + b  (mult = 2^k)
__device__ __forceinline__ uint32_t madp(uint32_t a, uint32_t mult, uint32_t b) {
    uint32_t d;
    asm("mad.lo.u32 %0, %1, %2, %3;" : "=r"(d) : "r"(a), "r"(mult), "r"(b));
    return d;
}

struct TSched {
    uint32_t a, b, c;
    uint32_t c1, a2, b3, c4, a5;   // k.c+1, k.a+2, k.b+3, k.c+4, k.a+5
};

__device__ __forceinline__ TSched mk_sched(uint32_t a, uint32_t b, uint32_t c) {
    TSched s; s.a = a; s.b = b; s.c = c;
    s.c1 = c + 1u; s.a2 = a + 2u; s.b3 = b + 3u; s.c4 = c + 4u; s.a5 = a + 5u;
    return s;
}

#define TFF_ROUND(x0, x1, r) { x0 = addf(x0, x1, one); x1 = __funnelshift_l(x1, x1, (r)); x1 ^= x0; }
#define TFF_R4A(x0, x1) { TFF_ROUND(x0,x1,13) TFF_ROUND(x0,x1,15) TFF_ROUND(x0,x1,26) TFF_ROUND(x0,x1,6) }
#define TFF_R4B(x0, x1) { TFF_ROUND(x0,x1,17) TFF_ROUND(x0,x1,29) TFF_ROUND(x0,x1,16) TFF_ROUND(x0,x1,24) }

// threefry2x32 at counter (0, idx): 20 SHF + 21 LOP3 (alu), 31 IMAD
__device__ __forceinline__ uint32_t tff_bits(const TSched k, uint32_t idx, uint32_t one) {
    uint32_t x0 = k.a, x1 = addf(idx, k.b, one);
    TFF_R4A(x0, x1); x0 = addf(x0, k.b, one); x1 = addf(x1, k.c1, one);
    TFF_R4B(x0, x1); x0 = addf(x0, k.c, one); x1 = addf(x1, k.a2, one);
    TFF_R4A(x0, x1); x0 = addf(x0, k.a, one); x1 = addf(x1, k.b3, one);
    TFF_R4B(x0, x1); x0 = addf(x0, k.b, one); x1 = addf(x1, k.c4, one);
    TFF_R4A(x0, x1); x0 = addf(x0, k.c, one); x1 = addf(x1, k.a5, one);
    return x0 ^ x1;
}

// Pre-shifted threshold: uniform(bits) < e  <=>  bits < (ceil(e*2^23) << 9).
__device__ __forceinline__ uint32_t thresh_shifted(float e) {
    return ((uint32_t)ceil((double)e * 8388608.0)) << 9;
}

// SWAR: per-2-bit-field (a + b) mod 4 over all 16 fields at once (4 LOP3).
__device__ __forceinline__ uint32_t add2bit_mod4(uint32_t a, uint32_t b) {
    const uint32_t t = a ^ b;
    const uint32_t cy = (a & b) & 0x55555555u;
    return t ^ (cy << 1);
}

// ============================================================================
// Per-channel key cache (keys depend only on channel c).
// ============================================================================

__device__ uint32_t g_keys[4][16];

__global__ void key_setup_kernel() {
    const int c = threadIdx.x;
    if (c >= 4) return;
    uint32_t t0, t1;
    const TKey root = mk_key(0u, 42u);
    tf_pair(root, 0u, (uint32_t)c, t0, t1);
    const TKey kc = mk_key(t0, t1);

    tf_pair(kc, 0u, 0u, t0, t1); const TKey s1 = mk_key(t0, t1);
    tf_pair(kc, 0u, 1u, t0, t1); const TKey s2 = mk_key(t0, t1);
    tf_pair(kc, 0u, 2u, t0, t1); const TKey s3 = mk_key(t0, t1);

    tf_pair(s1, 0u, 0u, t0, t1); const TKey sub_a = mk_key(t0, t1);
    tf_pair(sub_a, 0u, 1u, t0, t1); const TKey k_subdata = mk_key(t0, t1);
    tf_pair(s1, 0u, 1u, t0, t1); const TKey k_submask = mk_key(t0, t1);

    tf_pair(s3, 0u, 0u, t0, t1); const TKey k_insflag = mk_key(t0, t1);
    tf_pair(s3, 0u, 1u, t0, t1); const TKey ins_b = mk_key(t0, t1);
    tf_pair(ins_b, 0u, 1u, t0, t1); const TKey k_inssym = mk_key(t0, t1);

    uint32_t* kp = g_keys[c];
    kp[0] = k_submask.a; kp[1] = k_submask.b; kp[2] = k_submask.c;
    kp[3] = s2.a;        kp[4] = s2.b;        kp[5] = s2.c;
    kp[6] = k_subdata.a; kp[7] = k_subdata.b; kp[8] = k_subdata.c;
    kp[9] = k_insflag.a; kp[10] = k_insflag.b; kp[11] = k_insflag.c;
    kp[12] = k_inssym.a; kp[13] = k_inssym.b; kp[14] = k_inssym.c;
}

// ============================================================================
// Warp-per-(row, channel); lane owns 16 contiguous elements, 2-bit packed.
// ============================================================================

__global__ void __launch_bounds__(128)
channel_warp_kernel(const float* __restrict__ x, float* __restrict__ out, int B) {
    const int gw = (int)((blockIdx.x * blockDim.x + threadIdx.x) >> 5);
    const int lane = threadIdx.x & 31;
    if (gw >= B * 4) return;
    const int c = gw & 3;
    const int b = gw >> 2;

    const uint32_t KsubS = thresh_shifted(0.02f);
    const uint32_t KdelS = thresh_shifted(0.01f);
    const uint32_t KinsS = thresh_shifted(0.01f);

    const uint32_t* kp = g_keys[c];
    const uint32_t one = (kp[0] >> 31) | 1u;       // opaque runtime 1
    const TSched kSubM = mk_sched(kp[0], kp[1], kp[2]);
    const TSched kDel  = mk_sched(kp[3], kp[4], kp[5]);

    // ---- phase 1: sub-need + keep flags (unroll 4, ILP=8); no LDGs yet
    const uint32_t base = (uint32_t)b * 512u + (uint32_t)lane * 16u;
    uint32_t keepmask = 0u, subneed = 0u;
    {
        uint32_t bit = 1u;
        #pragma unroll 4
        for (int i = 0; i < 16; i++) {
            const uint32_t idx = base + (uint32_t)i;
            const uint32_t bs = tff_bits(kSubM, idx, one);
            const uint32_t bd = tff_bits(kDel,  idx, one);
            if (bs < KsubS)  subneed  |= bit;
            if (bd >= KdelS) keepmask |= bit;
            bit <<= 1;
        }
    }

    // ---- load input and pack to 2-bit codes (F2I + IMAD: all fma pipe).
    // One live register instead of 16; LDG latency hides behind sub/ins phases.
    uint32_t vpack = 0u;
    {
        const float4* __restrict__ xr4 =
            (const float4*)(x + (size_t)b * 512 + (size_t)lane * 16);
        #pragma unroll
        for (int q = 0; q < 4; q++) {
            const float4 f = xr4[q];
            const uint32_t c0 = (uint32_t)__float2int_rn(f.x);
            const uint32_t c1 = (uint32_t)__float2int_rn(f.y);
            const uint32_t c2 = (uint32_t)__float2int_rn(f.z);
            const uint32_t c3 = (uint32_t)__float2int_rn(f.w);
            vpack = madp(c0, (1u << (8 * q + 0)) * one, vpack);
            vpack = madp(c1, (1u << (8 * q + 2)) * one, vpack);
            vpack = madp(c2, (1u << (8 * q + 4)) * one, vpack);
            vpack = madp(c3, (1u << (8 * q + 6)) * one, vpack);
        }
    }

    // ---- deferred sub draws: per-lane bit loop, 2-bit packed deltas
    uint32_t subdelta = 0u;
    {
        const TSched kSubD = mk_sched(kp[6], kp[7], kp[8]);
        uint32_t m = subneed;
        while (m) {
            const int i = __ffs(m) - 1; m &= m - 1u;
            const uint32_t db = tff_bits(kSubD, base + (uint32_t)i, one);
            subdelta |= (db & 3u) << (2 * i);
        }
    }
    // ---- apply sub across all 16 fields at once (4 LOP3)
    uint32_t pk = add2bit_mod4(vpack, subdelta);

    // ---- scan 1: exclusive scan of keep counts -> compacted offset
    const int kn = __popc(keepmask);
    int incl = kn;
    #pragma unroll
    for (int d = 1; d < 32; d <<= 1) {
        const int nv = __shfl_up_sync(FULLM, incl, d);
        if (lane >= d) incl += nv;
    }
    const int ofs = incl - kn;

    // ---- phase 2: ins flags at compacted indices (iterative j, unroll 4)
    const uint32_t insbase = (uint32_t)b * 514u;
    uint32_t insmask = 0u;
    {
        const TSched kInsF = mk_sched(kp[9], kp[10], kp[11]);
        uint32_t km = keepmask, bit = 1u;
        uint32_t j = insbase + (uint32_t)ofs;
        #pragma unroll 4
        for (int i = 0; i < 16; i++) {
            const uint32_t bi = tff_bits(kInsF, j, one);
            if (bi < KinsS) insmask |= bit;
            j += km & 1u; km >>= 1; bit <<= 1;
        }
    }
    insmask &= keepmask;

    // ---- scan 2: output offsets
    const int myout = kn + __popc(insmask);
    int incl2 = myout;
    #pragma unroll
    for (int d = 1; d < 32; d <<= 1) {
        const int nv = __shfl_up_sync(FULLM, incl2, d);
        if (lane >= d) incl2 += nv;
    }
    const int outofs = incl2 - myout;
    const int total_out = __shfl_sync(FULLM, incl2, 31);

    float* __restrict__ orow = out + ((size_t)b * 4 + (size_t)c) * 514;

    // ---- write kept elements: extract 2-bit code (alu: SHF+LOP, same as
    // R13's sd handling) -> I2F + FADD (fma pipe). No mod-compare needed.
    {
        int pos = outofs;
        uint32_t km = keepmask, im = insmask;
        #pragma unroll
        for (int i = 0; i < 16; i++) {
            const float vv = (float)(pk & 3u) + 1.0f;   // code in [0,3] exact
            if ((km & 1u) && pos < 514) orow[pos] = vv;
            pos += (int)(km & 1u) + (int)(im & 1u);
            km >>= 1; im >>= 1; pk >>= 2;
        }
    }

    // ---- inserted symbols: rare per-lane bit loop
    {
        const TSched kInsS2 = mk_sched(kp[12], kp[13], kp[14]);
        uint32_t m = insmask;
        while (m) {
            const int i = __ffs(m) - 1; m &= m - 1u;
            const uint32_t below = (1u << i) - 1u;
            const int nk = __popc(keepmask & below);
            const uint32_t j = insbase + (uint32_t)(ofs + nk);
            const int pos = outofs + nk + __popc(insmask & below) + 1;
            const uint32_t sb = tff_bits(kInsS2, j, one);
            if (pos < 514) orow[pos] = (float)(sb & 3u) + 1.0f;
        }
    }

    // ---- tail padding: 0.0 (= -1 + 1)
    for (int p = total_out + lane; p < 514; p += 32) orow[p] = 0.0f;
}

extern "C" void kernel_launch(void* const* d_in, const int* in_sizes, int n_in,
                              void* d_out, int out_size) {
    const float* x = (const float*)d_in[0];   // segment_en [B, 512]
    float* out = (float*)d_out;               // [B, 4, 514] float32
    const int B = in_sizes[0] / 512;

    key_setup_kernel<<<1, 4>>>();

    const long long total_threads = (long long)B * 4 * 32;
    const int block = 128;
    const int grid = (int)((total_threads + block - 1) / block);
    channel_warp_kernel<<<grid, block>>>(x, out, B);
}